// round 15
// baseline (speedup 1.0000x reference)
#include <cuda_runtime.h>
#include <cuda_bf16.h>
#include <math.h>
#include <stdint.h>

#define N_NODES   50000
#define N_EDGES   1600000
#define N_GRAPHS  128
#define EDGE_DIM  43
#define KPAD      48
#define IN_DIM    35
#define HID       128
#define NSCB      ((N_NODES + 1023) / 1024)

// smem layout (bytes from dynamic base): ssrc 0..512, Ah 512, Al 14848, Bh 29184, Bl 43520 (end 57856)
// Zs (fp32 128x132) reuses 512..68096 after the MMA mainloop.
#define SM_SSRC   0
#define SM_AH     512
#define SM_AL     14848
#define SM_BH     29184
#define SM_BL     43520
#define SM_ZS     512
#define EDGE_SMEM 68608
#define ROWB      112            // 56 bf16 per row

// ---------------- scratch ----------------
__device__ __nv_bfloat16 g_attr_hi[(size_t)N_EDGES * KPAD];
__device__ __nv_bfloat16 g_attr_lo[(size_t)N_EDGES * KPAD];
__device__ __nv_bfloat16 g_wh[3][128 * KPAD];
__device__ __nv_bfloat16 g_wl[3][128 * KPAD];
__device__ int   g_src_s[N_EDGES];
__device__ int   g_perm[N_EDGES];
__device__ int   g_src32[N_EDGES];
__device__ int   g_deg[N_NODES];
__device__ int   g_cursor[N_NODES];
__device__ int   g_bsum[64];
__device__ int   g_boff[64];
__device__ int   g_flag_ei;
__device__ int   g_flag_b;
__device__ float g_A[(size_t)N_NODES * HID];
__device__ float g_hbuf[2][(size_t)N_NODES * HID];
__device__ float g_g1[(size_t)N_NODES * 64];
__device__ float g_g2[(size_t)N_NODES * 32];
__device__ float g_gate[N_NODES];
__device__ int   g_gcnt[N_GRAPHS];
__device__ int   g_gptr[N_GRAPHS + 1];
__device__ float g_emb[N_GRAPHS * HID];
__device__ float g_e2[N_GRAPHS * 256];
__device__ float g_o1[N_GRAPHS * 256];
__device__ float g_o2[N_GRAPHS * 128];
__device__ float g_o3[N_GRAPHS * 64];
__device__ float g_o4[N_GRAPHS * 4];

// ---------------- helpers ----------------
__device__ __forceinline__ float fast_tanh(float x) {
    float ax = fabsf(x);
    float t  = __expf(-2.0f * ax);
    float r  = __fdividef(1.0f - t, 1.0f + t);
    return copysignf(r, x);
}
__device__ __forceinline__ uint32_t smem_u32(const void* p) {
    uint32_t a;
    asm("{ .reg .u64 t; cvta.to.shared.u64 t, %1; cvt.u32.u64 %0, t; }" : "=r"(a) : "l"(p));
    return a;
}
#define LDMX4(r0, r1, r2, r3, addr) \
    asm volatile("ldmatrix.sync.aligned.m8n8.x4.shared.b16 {%0,%1,%2,%3}, [%4];" \
        : "=r"(r0), "=r"(r1), "=r"(r2), "=r"(r3) : "r"(addr))
#define MMA16816(d, a0, a1, a2, a3, b0, b1) \
    asm volatile("mma.sync.aligned.m16n8k16.row.col.f32.bf16.bf16.f32 " \
        "{%0,%1,%2,%3}, {%4,%5,%6,%7}, {%8,%9}, {%0,%1,%2,%3};" \
        : "+f"((d)[0]), "+f"((d)[1]), "+f"((d)[2]), "+f"((d)[3]) \
        : "r"(a0), "r"(a1), "r"(a2), "r"(a3), "r"(b0), "r"(b1))

// ---------------- dtype probes + CSR build ----------------
__global__ void k_zero() {
    int i = blockIdx.x * blockDim.x + threadIdx.x;
    if (i < N_NODES)  g_deg[i]  = 0;
    if (i < N_GRAPHS) g_gcnt[i] = 0;
    if (i == 0) { g_flag_ei = 1; g_flag_b = 1; }
}
__global__ void k_detect_ei(const void* __restrict__ ei) {
    int e = blockIdx.x * blockDim.x + threadIdx.x;
    if (e < N_EDGES) {
        long long v = ((const long long*)ei)[e];
        if (v < 0 || v >= N_NODES) g_flag_ei = 0;
    }
}
__global__ void k_detect_b(const void* __restrict__ b) {
    int i = blockIdx.x * blockDim.x + threadIdx.x;
    if (i < N_NODES / 2) {
        long long v = ((const long long*)b)[i];
        if (v < 0 || v >= N_GRAPHS) g_flag_b = 0;
    }
}
__global__ void k_hist(const void* __restrict__ ei) {
    int e = blockIdx.x * blockDim.x + threadIdx.x;
    if (e < N_EDGES) {
        int s = g_flag_ei ? (int)((const long long*)ei)[e] : ((const int*)ei)[e];
        if (s < 0) s = 0; else if (s >= N_NODES) s = N_NODES - 1;
        g_src32[e] = s;
        atomicAdd(&g_deg[s], 1);
    }
}
__global__ void k_scan1() {
    __shared__ int sh[1024];
    int b = blockIdx.x, t = threadIdx.x;
    int i = b * 1024 + t;
    int v = (i < N_NODES) ? g_deg[i] : 0;
    sh[t] = v;
    __syncthreads();
    for (int off = 1; off < 1024; off <<= 1) {
        int add = (t >= off) ? sh[t - off] : 0;
        __syncthreads();
        sh[t] += add;
        __syncthreads();
    }
    if (i < N_NODES) g_cursor[i] = sh[t] - v;
    if (t == 1023) g_bsum[b] = sh[1023];
}
__global__ void k_scan2() {
    if (threadIdx.x == 0 && blockIdx.x == 0) {
        int run = 0;
        for (int b = 0; b < NSCB; b++) { g_boff[b] = run; run += g_bsum[b]; }
    }
}
__global__ void k_scan3() {
    int i = blockIdx.x * blockDim.x + threadIdx.x;
    if (i < N_NODES) g_cursor[i] += g_boff[i >> 10];
}
__global__ void k_scatter() {
    int e = blockIdx.x * blockDim.x + threadIdx.x;
    if (e < N_EDGES) {
        int s = g_src32[e];
        int p = atomicAdd(&g_cursor[s], 1);
        if (p >= 0 && p < N_EDGES) { g_perm[p] = e; g_src_s[p] = s; }
    }
}
__global__ void k_permute_split(const float* __restrict__ attr) {
    int idx = blockIdx.x * blockDim.x + threadIdx.x;
    if (idx < N_EDGES * KPAD) {
        int p = idx / KPAD, c = idx - p * KPAD;
        float x = (c < EDGE_DIM) ? attr[(size_t)g_perm[p] * EDGE_DIM + c] : 0.f;
        __nv_bfloat16 h = __float2bfloat16(x);
        g_attr_hi[idx] = h;
        g_attr_lo[idx] = __float2bfloat16(x - __bfloat162float(h));
    }
}
__global__ void k_wsplit(const float* __restrict__ W, int ldw, int woff,
                         __nv_bfloat16* __restrict__ wh, __nv_bfloat16* __restrict__ wl) {
    int idx = blockIdx.x * blockDim.x + threadIdx.x;
    if (idx < 128 * KPAD) {
        int c = idx / KPAD, k = idx - c * KPAD;
        float x = (k < EDGE_DIM) ? W[c * ldw + woff + k] : 0.f;
        __nv_bfloat16 h = __float2bfloat16(x);
        wh[idx] = h;
        wl[idx] = __float2bfloat16(x - __bfloat162float(h));
    }
}

// ---------------- generic tiled linear (proven R5 version) ----------------
__global__ void k_linear(const float* __restrict__ X, const float* __restrict__ W,
                         const float* __restrict__ bias, float* __restrict__ Y,
                         int M, int N, int K, int ldw, int woff, int act)
{
    __shared__ __align__(16) float Xs[16][132];
    __shared__ __align__(16) float Ws[16][68];
    int tid = threadIdx.x;
    int M0 = blockIdx.x * 128;
    int N0 = blockIdx.y * 64;
    int ty = tid >> 4, tx = tid & 15;
    float acc[8][4];
#pragma unroll
    for (int i = 0; i < 8; i++)
#pragma unroll
        for (int j = 0; j < 4; j++) acc[i][j] = 0.f;

    for (int k0 = 0; k0 < K; k0 += 16) {
#pragma unroll
        for (int l = 0; l < 8; l++) {
            int idx = tid + l * 256;
            int m = idx >> 4, k = idx & 15;
            int gm = M0 + m, gk = k0 + k;
            Xs[k][m] = (gm < M && gk < K) ? X[(size_t)gm * K + gk] : 0.f;
        }
#pragma unroll
        for (int l = 0; l < 4; l++) {
            int idx = tid + l * 256;
            int n = idx >> 4, k = idx & 15;
            int gn = N0 + n, gk = k0 + k;
            Ws[k][n] = (gn < N && gk < K) ? W[gn * ldw + woff + gk] : 0.f;
        }
        __syncthreads();
#pragma unroll
        for (int kk = 0; kk < 16; kk++) {
            float4 a0 = *(const float4*)&Xs[kk][ty * 8];
            float4 a1 = *(const float4*)&Xs[kk][ty * 8 + 4];
            float4 w  = *(const float4*)&Ws[kk][tx * 4];
            float a[8] = {a0.x, a0.y, a0.z, a0.w, a1.x, a1.y, a1.z, a1.w};
            float wv[4] = {w.x, w.y, w.z, w.w};
#pragma unroll
            for (int i = 0; i < 8; i++)
#pragma unroll
                for (int j = 0; j < 4; j++) acc[i][j] += a[i] * wv[j];
        }
        __syncthreads();
    }
#pragma unroll
    for (int j = 0; j < 4; j++) {
        int gn = N0 + tx * 4 + j;
        if (gn >= N) continue;
        float b = bias[gn];
#pragma unroll
        for (int i = 0; i < 8; i++) {
            int gm = M0 + ty * 8 + i;
            if (gm >= M) continue;
            float v = acc[i][j] + b;
            if (act == 1)      v = fast_tanh(v);
            else if (act == 2) v = fmaxf(v, 0.f);
            Y[(size_t)gm * N + gn] = v;
        }
    }
}

// ---------------- HMMA bf16 edge GEMM + tanh + segment scatter ----------------
// Z[128e][128c] = attr @ W^T via mma.m16n8k16 bf16 (3-product split), then R5 epilogue.
__global__ void __launch_bounds__(256) k_edge_mma(
    const __nv_bfloat16* __restrict__ Wh, const __nv_bfloat16* __restrict__ Wl,
    const float* __restrict__ A, float* __restrict__ out)
{
    extern __shared__ __align__(16) char bp[];
    uint32_t sb = smem_u32(bp);
    int* ssrc = (int*)(bp + SM_SSRC);

    int tid = threadIdx.x, wid = tid >> 5, lid = tid & 31;
    int t0 = blockIdx.x * 128;                       // N_EDGES % 128 == 0

    if (tid < 128) ssrc[tid] = g_src_s[t0 + tid];

    // stage operands: rows of 24 words (96B) at 112B stride (words 24..27 unread)
    {
        const uint32_t* ah = (const uint32_t*)g_attr_hi + (size_t)t0 * 24;
        const uint32_t* al = (const uint32_t*)g_attr_lo + (size_t)t0 * 24;
        const uint32_t* bh = (const uint32_t*)Wh;
        const uint32_t* bl = (const uint32_t*)Wl;
        for (int idx = tid; idx < 128 * 24; idx += 256) {
            int r = idx / 24, w = idx - r * 24;
            int so = r * ROWB + w * 4;
            *(uint32_t*)(bp + SM_AH + so) = ah[idx];
            *(uint32_t*)(bp + SM_AL + so) = al[idx];
            *(uint32_t*)(bp + SM_BH + so) = bh[idx];
            *(uint32_t*)(bp + SM_BL + so) = bl[idx];
        }
    }
    __syncthreads();

    // warp tile: m-band (wid&3)*32, n-band (wid>>2)*64
    int m0 = (wid & 3) * 32;
    int n0 = (wid >> 2) * 64;
    float acc[2][8][4];
#pragma unroll
    for (int mt = 0; mt < 2; mt++)
#pragma unroll
        for (int nt = 0; nt < 8; nt++)
#pragma unroll
            for (int j = 0; j < 4; j++) acc[mt][nt][j] = 0.f;

    // lane addr components
    uint32_t aRow = (uint32_t)((lid & 15) * ROWB + (lid >> 4) * 16);
    uint32_t bRow = (uint32_t)((((lid & 7) | ((lid >> 4) << 3)) * ROWB) + (((lid >> 3) & 1) * 16));

    const uint32_t aBase[3] = { sb + SM_AH, sb + SM_AH, sb + SM_AL };
    const uint32_t bBase[3] = { sb + SM_BH, sb + SM_BL, sb + SM_BH };

#pragma unroll
    for (int pr = 0; pr < 3; pr++) {
        uint32_t abp = aBase[pr] + aRow;
        uint32_t bbp = bBase[pr] + bRow;
#pragma unroll
        for (int ks = 0; ks < 3; ks++) {
            uint32_t a0[4], a1[4];
            LDMX4(a0[0], a0[1], a0[2], a0[3], abp + m0 * ROWB + ks * 32);
            LDMX4(a1[0], a1[1], a1[2], a1[3], abp + (m0 + 16) * ROWB + ks * 32);
            uint32_t bf[4][4];   // 4 pairs x (2 n8-tiles x 2 regs)
#pragma unroll
            for (int p = 0; p < 4; p++)
                LDMX4(bf[p][0], bf[p][1], bf[p][2], bf[p][3],
                      bbp + (n0 + p * 16) * ROWB + ks * 32);
#pragma unroll
            for (int p = 0; p < 4; p++) {
                MMA16816(acc[0][p * 2 + 0], a0[0], a0[1], a0[2], a0[3], bf[p][0], bf[p][1]);
                MMA16816(acc[0][p * 2 + 1], a0[0], a0[1], a0[2], a0[3], bf[p][2], bf[p][3]);
                MMA16816(acc[1][p * 2 + 0], a1[0], a1[1], a1[2], a1[3], bf[p][0], bf[p][1]);
                MMA16816(acc[1][p * 2 + 1], a1[0], a1[1], a1[2], a1[3], bf[p][2], bf[p][3]);
            }
        }
    }
    __syncthreads();   // operands dead; reuse region as Zs

    // fragment -> Zs[128][132]
    float* Zs = (float*)(bp + SM_ZS);
    {
        int gl = lid >> 2;
        int gc = (lid & 3) * 2;
#pragma unroll
        for (int mt = 0; mt < 2; mt++) {
#pragma unroll
            for (int nt = 0; nt < 8; nt++) {
                float* z0 = Zs + (size_t)(m0 + mt * 16 + gl) * 132 + n0 + nt * 8 + gc;
                z0[0] = acc[mt][nt][0];
                z0[1] = acc[mt][nt][1];
                float* z1 = z0 + 8 * 132;
                z1[0] = acc[mt][nt][2];
                z1[1] = acc[mt][nt][3];
            }
        }
    }
    __syncthreads();

    // epilogue: R5 run-length segment reduce (thread = 8 sorted edges x 8 channels)
    int ty = tid >> 4, tx = tid & 15;
    float part[8], areg[8];
    int prev = -1;
#pragma unroll
    for (int i = 0; i < 8; i++) {
        int e = ty * 8 + i;
        int s = ssrc[e];
        if (s != prev) {
            if (prev >= 0) {
                float* op = out + (size_t)prev * HID + tx * 8;
#pragma unroll
                for (int j = 0; j < 8; j++) atomicAdd(op + j, part[j]);
            }
            prev = s;
            const float4* Ap = (const float4*)(A + (size_t)s * HID + tx * 8);
            float4 v0 = Ap[0], v1 = Ap[1];
            areg[0] = v0.x; areg[1] = v0.y; areg[2] = v0.z; areg[3] = v0.w;
            areg[4] = v1.x; areg[5] = v1.y; areg[6] = v1.z; areg[7] = v1.w;
#pragma unroll
            for (int j = 0; j < 8; j++) part[j] = 0.f;
        }
        const float* zr = Zs + (size_t)e * 132 + tx * 8;
#pragma unroll
        for (int j = 0; j < 8; j++) part[j] += fast_tanh(zr[j] + areg[j]);
    }
    {
        float* op = out + (size_t)prev * HID + tx * 8;
#pragma unroll
        for (int j = 0; j < 8; j++) atomicAdd(op + j, part[j]);
    }
}

// ---------------- graph segmentation + attention readout ----------------
__global__ void k_gcnt(const void* __restrict__ batch) {
    int n = blockIdx.x * blockDim.x + threadIdx.x;
    if (n < N_NODES) {
        int g = g_flag_b ? (int)((const long long*)batch)[n] : ((const int*)batch)[n];
        if (g < 0) g = 0; else if (g >= N_GRAPHS) g = N_GRAPHS - 1;
        atomicAdd(&g_gcnt[g], 1);
    }
}
__global__ void k_gscan() {
    if (threadIdx.x == 0 && blockIdx.x == 0) {
        int run = 0;
        g_gptr[0] = 0;
        for (int g = 0; g < N_GRAPHS; g++) { run += g_gcnt[g]; g_gptr[g + 1] = run; }
    }
}
__global__ void k_attn(const float* __restrict__ h, float* __restrict__ attout) {
    int g = blockIdx.x, t = threadIdx.x;
    int lo = g_gptr[g], hi = g_gptr[g + 1];
    __shared__ float red[128];
    float m = -1e30f;
    for (int n = lo + t; n < hi; n += 128) m = fmaxf(m, g_gate[n]);
    red[t] = m; __syncthreads();
    for (int s = 64; s > 0; s >>= 1) { if (t < s) red[t] = fmaxf(red[t], red[t + s]); __syncthreads(); }
    m = red[0]; __syncthreads();
    float sum = 0.f;
    for (int n = lo + t; n < hi; n += 128) sum += __expf(g_gate[n] - m);
    red[t] = sum; __syncthreads();
    for (int s = 64; s > 0; s >>= 1) { if (t < s) red[t] += red[t + s]; __syncthreads(); }
    float inv = 1.0f / (red[0] + 1e-16f);
    for (int n = lo + t; n < hi; n += 128) attout[n] = __expf(g_gate[n] - m) * inv;
    float a0 = 0.f, a1 = 0.f, a2 = 0.f, a3 = 0.f;
    int n = lo;
    for (; n + 3 < hi; n += 4) {
        float w0 = __expf(g_gate[n]     - m) * inv;
        float w1 = __expf(g_gate[n + 1] - m) * inv;
        float w2 = __expf(g_gate[n + 2] - m) * inv;
        float w3 = __expf(g_gate[n + 3] - m) * inv;
        a0 += w0 * h[(size_t)n * HID + t];
        a1 += w1 * h[(size_t)(n + 1) * HID + t];
        a2 += w2 * h[(size_t)(n + 2) * HID + t];
        a3 += w3 * h[(size_t)(n + 3) * HID + t];
    }
    for (; n < hi; n++) a0 += __expf(g_gate[n] - m) * inv * h[(size_t)n * HID + t];
    g_emb[g * HID + t] = (a0 + a1) + (a2 + a3);
}
__global__ void k_concat(const float* __restrict__ us, const float* __restrict__ ud) {
    int idx = blockIdx.x * blockDim.x + threadIdx.x;
    if (idx < N_GRAPHS * 256) {
        int g = idx >> 8, c = idx & 255;
        float v;
        if (c < 128)      v = g_emb[g * 128 + c];
        else if (c < 192) v = us[g * 64 + (c - 128)];
        else              v = ud[g * 64 + (c - 192)];
        g_e2[idx] = v;
    }
}
__global__ void k_out(float* __restrict__ out) {
    int g = threadIdx.x;
    if (g < N_GRAPHS) {
        float s = 0.f;
#pragma unroll
        for (int j = 0; j < 4; j++) { float v = g_o4[g * 4 + j]; out[g * 5 + j] = v; s += v; }
        out[g * 5 + 4] = s;
    }
}

// ---------------- driver ----------------
extern "C" void kernel_launch(void* const* d_in, const int* in_sizes, int n_in,
                              void* d_out, int out_size)
{
    const float* x        = (const float*)d_in[0];
    const float* edge_attr= (const float*)d_in[1];
    const float* u_soap   = (const float*)d_in[2];
    const float* u_dimer  = (const float*)d_in[3];
    const float* W1n = (const float*)d_in[4];  const float* b1n = (const float*)d_in[5];
    const float* W1r = (const float*)d_in[6];  const float* b1r = (const float*)d_in[7];
    const float* W2n = (const float*)d_in[8];  const float* b2n = (const float*)d_in[9];
    const float* W2r = (const float*)d_in[10]; const float* b2r = (const float*)d_in[11];
    const float* W3n = (const float*)d_in[12]; const float* b3n = (const float*)d_in[13];
    const float* W3r = (const float*)d_in[14]; const float* b3r = (const float*)d_in[15];
    const float* Wg1 = (const float*)d_in[16]; const float* bg1 = (const float*)d_in[17];
    const float* Wg2 = (const float*)d_in[18]; const float* bg2 = (const float*)d_in[19];
    const float* Wg3 = (const float*)d_in[20]; const float* bg3 = (const float*)d_in[21];
    const float* Wl1 = (const float*)d_in[22]; const float* bl1 = (const float*)d_in[23];
    const float* Wl2 = (const float*)d_in[24]; const float* bl2 = (const float*)d_in[25];
    const float* Wl3 = (const float*)d_in[26]; const float* bl3 = (const float*)d_in[27];
    const float* Wl  = (const float*)d_in[28]; const float* bl  = (const float*)d_in[29];
    const void*  edge_index = d_in[30];
    const void*  batch      = d_in[31];
    float* out = (float*)d_out;

    float *pA, *ph, *pg1, *pg2, *pgate, *pe2, *po1, *po2, *po3, *po4;
    __nv_bfloat16 *pwh, *pwl;
    cudaGetSymbolAddress((void**)&pA,    g_A);
    cudaGetSymbolAddress((void**)&ph,    g_hbuf);
    cudaGetSymbolAddress((void**)&pg1,   g_g1);
    cudaGetSymbolAddress((void**)&pg2,   g_g2);
    cudaGetSymbolAddress((void**)&pgate, g_gate);
    cudaGetSymbolAddress((void**)&pe2,   g_e2);
    cudaGetSymbolAddress((void**)&po1,   g_o1);
    cudaGetSymbolAddress((void**)&po2,   g_o2);
    cudaGetSymbolAddress((void**)&po3,   g_o3);
    cudaGetSymbolAddress((void**)&po4,   g_o4);
    cudaGetSymbolAddress((void**)&pwh,   g_wh);
    cudaGetSymbolAddress((void**)&pwl,   g_wl);
    float* ph0 = ph;
    float* ph1 = ph + (size_t)N_NODES * HID;

    cudaFuncSetAttribute(k_edge_mma, cudaFuncAttributeMaxDynamicSharedMemorySize, EDGE_SMEM);

    const int NB_M = (N_NODES + 127) / 128;            // 391
    const int EB   = (N_EDGES + 127) / 128;            // 12500
    const int WSB  = (128 * KPAD + 255) / 256;

    // dtype probes + CSR build + splits
    k_zero       <<<(N_NODES + 255) / 256, 256>>>();
    k_detect_ei  <<<(N_EDGES + 255) / 256, 256>>>(edge_index);
    k_detect_b   <<<(N_NODES / 2 + 255) / 256, 256>>>(batch);
    k_hist       <<<(N_EDGES + 255) / 256, 256>>>(edge_index);
    k_scan1      <<<NSCB, 1024>>>();
    k_scan2      <<<1, 32>>>();
    k_scan3      <<<(N_NODES + 255) / 256, 256>>>();
    k_scatter    <<<(N_EDGES + 255) / 256, 256>>>();
    k_permute_split<<<(N_EDGES * KPAD + 255) / 256, 256>>>(edge_attr);
    k_wsplit     <<<WSB, 256>>>(W1n, IN_DIM + EDGE_DIM, IN_DIM, pwh,              pwl);
    k_wsplit     <<<WSB, 256>>>(W2n, HID + EDGE_DIM,    HID,    pwh + 128 * KPAD, pwl + 128 * KPAD);
    k_wsplit     <<<WSB, 256>>>(W3n, HID + EDGE_DIM,    HID,    pwh + 256 * KPAD, pwl + 256 * KPAD);

    // layer 1
    k_linear<<<dim3(NB_M, 2), 256>>>(x,   W1n, b1n, pA,  N_NODES, 128, IN_DIM, IN_DIM + EDGE_DIM, 0, 0);
    k_linear<<<dim3(NB_M, 2), 256>>>(x,   W1r, b1r, ph0, N_NODES, 128, IN_DIM, IN_DIM,            0, 1);
    k_edge_mma<<<EB, 256, EDGE_SMEM>>>(pwh,              pwl,              pA, ph0);

    // layer 2
    k_linear<<<dim3(NB_M, 2), 256>>>(ph0, W2n, b2n, pA,  N_NODES, 128, HID, HID + EDGE_DIM, 0, 0);
    k_linear<<<dim3(NB_M, 2), 256>>>(ph0, W2r, b2r, ph1, N_NODES, 128, HID, HID,            0, 1);
    k_edge_mma<<<EB, 256, EDGE_SMEM>>>(pwh + 128 * KPAD, pwl + 128 * KPAD, pA, ph1);

    // layer 3
    k_linear<<<dim3(NB_M, 2), 256>>>(ph1, W3n, b3n, pA,  N_NODES, 128, HID, HID + EDGE_DIM, 0, 0);
    k_linear<<<dim3(NB_M, 2), 256>>>(ph1, W3r, b3r, ph0, N_NODES, 128, HID, HID,            0, 1);
    k_edge_mma<<<EB, 256, EDGE_SMEM>>>(pwh + 256 * KPAD, pwl + 256 * KPAD, pA, ph0);

    // gate MLP
    k_linear<<<dim3(NB_M, 1), 256>>>(ph0, Wg1, bg1, pg1,   N_NODES, 64, 128, 128, 0, 2);
    k_linear<<<dim3(NB_M, 1), 256>>>(pg1, Wg2, bg2, pg2,   N_NODES, 32, 64,  64,  0, 2);
    k_linear<<<dim3(NB_M, 1), 256>>>(pg2, Wg3, bg3, pgate, N_NODES, 1,  32,  32,  0, 0);

    // graph segments + attention readout
    k_gcnt <<<(N_NODES + 255) / 256, 256>>>(batch);
    k_gscan<<<1, 32>>>();
    k_attn <<<N_GRAPHS, 128>>>(ph0, out + N_GRAPHS * 5);

    // head MLP
    k_concat<<<(N_GRAPHS * 256 + 255) / 256, 256>>>(u_soap, u_dimer);
    k_linear<<<dim3(1, 4), 256>>>(pe2, Wl1, bl1, po1, N_GRAPHS, 256, 256, 256, 0, 2);
    k_linear<<<dim3(1, 2), 256>>>(po1, Wl2, bl2, po2, N_GRAPHS, 128, 256, 256, 0, 2);
    k_linear<<<dim3(1, 1), 256>>>(po2, Wl3, bl3, po3, N_GRAPHS, 64,  128, 128, 0, 2);
    k_linear<<<dim3(1, 1), 256>>>(po3, Wl,  bl,  po4, N_GRAPHS, 4,   64,  64,  0, 0);
    k_out<<<1, 128>>>(out);
}

// round 16
// speedup vs baseline: 1.4065x; 1.4065x over previous
#include <cuda_runtime.h>
#include <cuda_bf16.h>
#include <math.h>

#define N_NODES   50000
#define N_EDGES   1600000
#define N_GRAPHS  128
#define EDGE_DIM  43
#define IN_DIM    35
#define HID       128
#define NSCB      ((N_NODES + 1023) / 1024)   // 49 scan blocks

// ---------------- scratch (device globals: sanctioned scratch mechanism) ----------------
__device__ float g_attr_s[(size_t)N_EDGES * EDGE_DIM];   // sorted edge_attr (275MB)
__device__ int   g_src_s[N_EDGES];
__device__ int   g_perm[N_EDGES];
__device__ int   g_src32[N_EDGES];
__device__ int   g_deg[N_NODES];
__device__ int   g_cursor[N_NODES];
__device__ int   g_bsum[64];
__device__ int   g_boff[64];
__device__ int   g_flag_ei;      // 1 = edge_index is int64
__device__ int   g_flag_b;       // 1 = batch is int64
__device__ float g_A[(size_t)N_NODES * HID];             // per-node edge-side pre-activation
__device__ float g_hbuf[2][(size_t)N_NODES * HID];
__device__ float g_g1[(size_t)N_NODES * 64];
__device__ float g_g2[(size_t)N_NODES * 32];
__device__ float g_gate[N_NODES];
__device__ int   g_gcnt[N_GRAPHS];
__device__ int   g_gptr[N_GRAPHS + 1];
__device__ float g_emb[N_GRAPHS * HID];
__device__ float g_e2[N_GRAPHS * 256];
__device__ float g_o1[N_GRAPHS * 256];
__device__ float g_o2[N_GRAPHS * 128];
__device__ float g_o3[N_GRAPHS * 64];
__device__ float g_o4[N_GRAPHS * 4];

// ---------------- helpers ----------------
// tanh with 1 MUFU (EX2): reciprocal of d=1+t on the FMA pipe (seed + 2 Newton steps).
__device__ __forceinline__ float fast_tanh(float x) {
    float ax = fabsf(x);
    float t  = __expf(-2.0f * ax);
    float d  = 1.0f + t;
    float r  = fmaf(-0.5f, d, 1.45711f);
    r = r * fmaf(-d, r, 2.0f);
    r = r * fmaf(-d, r, 2.0f);
    float res = (1.0f - t) * r;
    return copysignf(res, x);
}

// ---------------- dtype probes + CSR build ----------------
__global__ void k_zero() {
    int i = blockIdx.x * blockDim.x + threadIdx.x;
    if (i < N_NODES)  g_deg[i]  = 0;
    if (i < N_GRAPHS) g_gcnt[i] = 0;
    if (i == 0) { g_flag_ei = 1; g_flag_b = 1; }
}
__global__ void k_detect_ei(const void* __restrict__ ei) {
    int e = blockIdx.x * blockDim.x + threadIdx.x;
    if (e < N_EDGES) {
        long long v = ((const long long*)ei)[e];
        if (v < 0 || v >= N_NODES) g_flag_ei = 0;
    }
}
__global__ void k_detect_b(const void* __restrict__ b) {
    int i = blockIdx.x * blockDim.x + threadIdx.x;
    if (i < N_NODES / 2) {
        long long v = ((const long long*)b)[i];
        if (v < 0 || v >= N_GRAPHS) g_flag_b = 0;
    }
}
__global__ void k_hist(const void* __restrict__ ei) {
    int e = blockIdx.x * blockDim.x + threadIdx.x;
    if (e < N_EDGES) {
        int s = g_flag_ei ? (int)((const long long*)ei)[e] : ((const int*)ei)[e];
        if (s < 0) s = 0; else if (s >= N_NODES) s = N_NODES - 1;
        g_src32[e] = s;
        atomicAdd(&g_deg[s], 1);
    }
}
__global__ void k_scan1() {
    __shared__ int sh[1024];
    int b = blockIdx.x, t = threadIdx.x;
    int i = b * 1024 + t;
    int v = (i < N_NODES) ? g_deg[i] : 0;
    sh[t] = v;
    __syncthreads();
    for (int off = 1; off < 1024; off <<= 1) {
        int add = (t >= off) ? sh[t - off] : 0;
        __syncthreads();
        sh[t] += add;
        __syncthreads();
    }
    if (i < N_NODES) g_cursor[i] = sh[t] - v;
    if (t == 1023) g_bsum[b] = sh[1023];
}
__global__ void k_scan2() {
    if (threadIdx.x == 0 && blockIdx.x == 0) {
        int run = 0;
        for (int b = 0; b < NSCB; b++) { g_boff[b] = run; run += g_bsum[b]; }
    }
}
__global__ void k_scan3() {
    int i = blockIdx.x * blockDim.x + threadIdx.x;
    if (i < N_NODES) g_cursor[i] += g_boff[i >> 10];
}
__global__ void k_scatter() {
    int e = blockIdx.x * blockDim.x + threadIdx.x;
    if (e < N_EDGES) {
        int s = g_src32[e];
        int p = atomicAdd(&g_cursor[s], 1);
        if (p >= 0 && p < N_EDGES) { g_perm[p] = e; g_src_s[p] = s; }
    }
}
__global__ void k_permute(const float* __restrict__ attr) {
    int idx = blockIdx.x * blockDim.x + threadIdx.x;
    if (idx < N_EDGES * EDGE_DIM) {
        int p = idx / EDGE_DIM;
        int c = idx - p * EDGE_DIM;
        g_attr_s[idx] = attr[(size_t)g_perm[p] * EDGE_DIM + c];
    }
}

// ---------------- generic tiled linear (proven R5 version) ----------------
__global__ void k_linear(const float* __restrict__ X, const float* __restrict__ W,
                         const float* __restrict__ bias, float* __restrict__ Y,
                         int M, int N, int K, int ldw, int woff, int act)
{
    __shared__ __align__(16) float Xs[16][132];
    __shared__ __align__(16) float Ws[16][68];
    int tid = threadIdx.x;
    int M0 = blockIdx.x * 128;
    int N0 = blockIdx.y * 64;
    int ty = tid >> 4, tx = tid & 15;
    float acc[8][4];
#pragma unroll
    for (int i = 0; i < 8; i++)
#pragma unroll
        for (int j = 0; j < 4; j++) acc[i][j] = 0.f;

    for (int k0 = 0; k0 < K; k0 += 16) {
#pragma unroll
        for (int l = 0; l < 8; l++) {
            int idx = tid + l * 256;
            int m = idx >> 4, k = idx & 15;
            int gm = M0 + m, gk = k0 + k;
            Xs[k][m] = (gm < M && gk < K) ? X[(size_t)gm * K + gk] : 0.f;
        }
#pragma unroll
        for (int l = 0; l < 4; l++) {
            int idx = tid + l * 256;
            int n = idx >> 4, k = idx & 15;
            int gn = N0 + n, gk = k0 + k;
            Ws[k][n] = (gn < N && gk < K) ? W[gn * ldw + woff + gk] : 0.f;
        }
        __syncthreads();
#pragma unroll
        for (int kk = 0; kk < 16; kk++) {
            float4 a0 = *(const float4*)&Xs[kk][ty * 8];
            float4 a1 = *(const float4*)&Xs[kk][ty * 8 + 4];
            float4 w  = *(const float4*)&Ws[kk][tx * 4];
            float a[8] = {a0.x, a0.y, a0.z, a0.w, a1.x, a1.y, a1.z, a1.w};
            float wv[4] = {w.x, w.y, w.z, w.w};
#pragma unroll
            for (int i = 0; i < 8; i++)
#pragma unroll
                for (int j = 0; j < 4; j++) acc[i][j] += a[i] * wv[j];
        }
        __syncthreads();
    }
#pragma unroll
    for (int j = 0; j < 4; j++) {
        int gn = N0 + tx * 4 + j;
        if (gn >= N) continue;
        float b = bias[gn];
#pragma unroll
        for (int i = 0; i < 8; i++) {
            int gm = M0 + ty * 8 + i;
            if (gm >= M) continue;
            float v = acc[i][j] + b;
            if (act == 1)      v = fast_tanh(v);
            else if (act == 2) v = fmaxf(v, 0.f);
            Y[(size_t)gm * N + gn] = v;
        }
    }
}

// ---------------- fused edge GEMM + tanh + segment scatter (occupancy-tuned) ----------------
// 512 threads, 2 CTA/SM target. Tile: 128 edges x 128 channels.
// warp = one 8-edge group (ty = tid>>5): As loads broadcast within warp.
// lane tx = tid&31 -> channel quad tx*4: Ws[k][tx*4] is 512B/warp, conflict-free.
// Per thread: acc[8][4] (32 regs), 32 FMA + 3 LDS per k-step.
__global__ void __launch_bounds__(512, 2) k_edge_conv(
    const float* __restrict__ W, int ldw, int woff,
    const float* __restrict__ A, float* __restrict__ out)
{
    __shared__ __align__(16) float As[EDGE_DIM][132];   // [k][edge]
    __shared__ __align__(16) float Ws[EDGE_DIM][132];   // [k][channel]
    __shared__ int ssrc[128];
    int tid = threadIdx.x;
    int t0  = blockIdx.x * 128;                         // N_EDGES % 128 == 0
    const float* attrBase = g_attr_s + (size_t)t0 * EDGE_DIM;
    for (int idx = tid; idx < 128 * EDGE_DIM; idx += 512) {
        int e = idx / EDGE_DIM;
        int k = idx - e * EDGE_DIM;
        As[k][e] = attrBase[idx];
    }
    for (int idx = tid; idx < 128 * EDGE_DIM; idx += 512) {
        int c = idx / EDGE_DIM;
        int k = idx - c * EDGE_DIM;
        Ws[k][c] = W[c * ldw + woff + k];
    }
    if (tid < 128) ssrc[tid] = g_src_s[t0 + tid];
    __syncthreads();

    int ty = tid >> 5;          // 0..15 -> 8-edge group
    int tx = tid & 31;          // channel quad tx*4
    int e0 = ty * 8;
    int c0 = tx * 4;

    float acc[8][4];
#pragma unroll
    for (int i = 0; i < 8; i++)
#pragma unroll
        for (int j = 0; j < 4; j++) acc[i][j] = 0.f;

#pragma unroll 1
    for (int k = 0; k < EDGE_DIM; k++) {
        float4 a0 = *(const float4*)&As[k][e0];         // broadcast within warp
        float4 a1 = *(const float4*)&As[k][e0 + 4];     // broadcast within warp
        float4 w  = *(const float4*)&Ws[k][c0];         // conflict-free
        float a[8] = {a0.x, a0.y, a0.z, a0.w, a1.x, a1.y, a1.z, a1.w};
        float wv[4] = {w.x, w.y, w.z, w.w};
#pragma unroll
        for (int i = 0; i < 8; i++)
#pragma unroll
            for (int j = 0; j < 4; j++) acc[i][j] += a[i] * wv[j];
    }

    // epilogue: per-thread run-length segment reduce over 8 sorted edges x 4 channels
    float part[4], areg[4];
    int prev = -1;
#pragma unroll
    for (int i = 0; i < 8; i++) {
        int s = ssrc[e0 + i];
        if (s != prev) {
            if (prev >= 0) {
                float* op = out + (size_t)prev * HID + c0;
#pragma unroll
                for (int j = 0; j < 4; j++) atomicAdd(op + j, part[j]);
            }
            prev = s;
            float4 v = *(const float4*)(A + (size_t)s * HID + c0);   // coalesced across warp
            areg[0] = v.x; areg[1] = v.y; areg[2] = v.z; areg[3] = v.w;
#pragma unroll
            for (int j = 0; j < 4; j++) part[j] = 0.f;
        }
#pragma unroll
        for (int j = 0; j < 4; j++) part[j] += fast_tanh(acc[i][j] + areg[j]);
    }
    {
        float* op = out + (size_t)prev * HID + c0;
#pragma unroll
        for (int j = 0; j < 4; j++) atomicAdd(op + j, part[j]);
    }
}

// ---------------- graph segmentation + attention readout ----------------
__global__ void k_gcnt(const void* __restrict__ batch) {
    int n = blockIdx.x * blockDim.x + threadIdx.x;
    if (n < N_NODES) {
        int g = g_flag_b ? (int)((const long long*)batch)[n] : ((const int*)batch)[n];
        if (g < 0) g = 0; else if (g >= N_GRAPHS) g = N_GRAPHS - 1;
        atomicAdd(&g_gcnt[g], 1);
    }
}
__global__ void k_gscan() {
    if (threadIdx.x == 0 && blockIdx.x == 0) {
        int run = 0;
        g_gptr[0] = 0;
        for (int g = 0; g < N_GRAPHS; g++) { run += g_gcnt[g]; g_gptr[g + 1] = run; }
    }
}
__global__ void k_attn(const float* __restrict__ h, float* __restrict__ attout) {
    int g = blockIdx.x, t = threadIdx.x;
    int lo = g_gptr[g], hi = g_gptr[g + 1];
    __shared__ float red[128];
    float m = -1e30f;
    for (int n = lo + t; n < hi; n += 128) m = fmaxf(m, g_gate[n]);
    red[t] = m; __syncthreads();
    for (int s = 64; s > 0; s >>= 1) { if (t < s) red[t] = fmaxf(red[t], red[t + s]); __syncthreads(); }
    m = red[0]; __syncthreads();
    float sum = 0.f;
    for (int n = lo + t; n < hi; n += 128) sum += __expf(g_gate[n] - m);
    red[t] = sum; __syncthreads();
    for (int s = 64; s > 0; s >>= 1) { if (t < s) red[t] += red[t + s]; __syncthreads(); }
    float inv = 1.0f / (red[0] + 1e-16f);
    for (int n = lo + t; n < hi; n += 128) attout[n] = __expf(g_gate[n] - m) * inv;
    float a0 = 0.f, a1 = 0.f, a2 = 0.f, a3 = 0.f;
    int n = lo;
    for (; n + 3 < hi; n += 4) {
        float w0 = __expf(g_gate[n]     - m) * inv;
        float w1 = __expf(g_gate[n + 1] - m) * inv;
        float w2 = __expf(g_gate[n + 2] - m) * inv;
        float w3 = __expf(g_gate[n + 3] - m) * inv;
        a0 += w0 * h[(size_t)n * HID + t];
        a1 += w1 * h[(size_t)(n + 1) * HID + t];
        a2 += w2 * h[(size_t)(n + 2) * HID + t];
        a3 += w3 * h[(size_t)(n + 3) * HID + t];
    }
    for (; n < hi; n++) a0 += __expf(g_gate[n] - m) * inv * h[(size_t)n * HID + t];
    g_emb[g * HID + t] = (a0 + a1) + (a2 + a3);
}
__global__ void k_concat(const float* __restrict__ us, const float* __restrict__ ud) {
    int idx = blockIdx.x * blockDim.x + threadIdx.x;
    if (idx < N_GRAPHS * 256) {
        int g = idx >> 8, c = idx & 255;
        float v;
        if (c < 128)      v = g_emb[g * 128 + c];
        else if (c < 192) v = us[g * 64 + (c - 128)];
        else              v = ud[g * 64 + (c - 192)];
        g_e2[idx] = v;
    }
}
__global__ void k_out(float* __restrict__ out) {
    int g = threadIdx.x;
    if (g < N_GRAPHS) {
        float s = 0.f;
#pragma unroll
        for (int j = 0; j < 4; j++) { float v = g_o4[g * 4 + j]; out[g * 5 + j] = v; s += v; }
        out[g * 5 + 4] = s;
    }
}

// ---------------- driver ----------------
extern "C" void kernel_launch(void* const* d_in, const int* in_sizes, int n_in,
                              void* d_out, int out_size)
{
    const float* x        = (const float*)d_in[0];
    const float* edge_attr= (const float*)d_in[1];
    const float* u_soap   = (const float*)d_in[2];
    const float* u_dimer  = (const float*)d_in[3];
    const float* W1n = (const float*)d_in[4];  const float* b1n = (const float*)d_in[5];
    const float* W1r = (const float*)d_in[6];  const float* b1r = (const float*)d_in[7];
    const float* W2n = (const float*)d_in[8];  const float* b2n = (const float*)d_in[9];
    const float* W2r = (const float*)d_in[10]; const float* b2r = (const float*)d_in[11];
    const float* W3n = (const float*)d_in[12]; const float* b3n = (const float*)d_in[13];
    const float* W3r = (const float*)d_in[14]; const float* b3r = (const float*)d_in[15];
    const float* Wg1 = (const float*)d_in[16]; const float* bg1 = (const float*)d_in[17];
    const float* Wg2 = (const float*)d_in[18]; const float* bg2 = (const float*)d_in[19];
    const float* Wg3 = (const float*)d_in[20]; const float* bg3 = (const float*)d_in[21];
    const float* Wl1 = (const float*)d_in[22]; const float* bl1 = (const float*)d_in[23];
    const float* Wl2 = (const float*)d_in[24]; const float* bl2 = (const float*)d_in[25];
    const float* Wl3 = (const float*)d_in[26]; const float* bl3 = (const float*)d_in[27];
    const float* Wl  = (const float*)d_in[28]; const float* bl  = (const float*)d_in[29];
    const void*  edge_index = d_in[30];
    const void*  batch      = d_in[31];
    float* out = (float*)d_out;

    float *pA, *ph, *pg1, *pg2, *pgate, *pe2, *po1, *po2, *po3, *po4;
    cudaGetSymbolAddress((void**)&pA,    g_A);
    cudaGetSymbolAddress((void**)&ph,    g_hbuf);
    cudaGetSymbolAddress((void**)&pg1,   g_g1);
    cudaGetSymbolAddress((void**)&pg2,   g_g2);
    cudaGetSymbolAddress((void**)&pgate, g_gate);
    cudaGetSymbolAddress((void**)&pe2,   g_e2);
    cudaGetSymbolAddress((void**)&po1,   g_o1);
    cudaGetSymbolAddress((void**)&po2,   g_o2);
    cudaGetSymbolAddress((void**)&po3,   g_o3);
    cudaGetSymbolAddress((void**)&po4,   g_o4);
    float* ph0 = ph;
    float* ph1 = ph + (size_t)N_NODES * HID;

    const int NB_M = (N_NODES + 127) / 128;            // 391
    const int EB   = (N_EDGES + 127) / 128;            // 12500

    // dtype probes + CSR build
    k_zero     <<<(N_NODES + 255) / 256, 256>>>();
    k_detect_ei<<<(N_EDGES + 255) / 256, 256>>>(edge_index);
    k_detect_b <<<(N_NODES / 2 + 255) / 256, 256>>>(batch);
    k_hist     <<<(N_EDGES + 255) / 256, 256>>>(edge_index);
    k_scan1    <<<NSCB, 1024>>>();
    k_scan2    <<<1, 32>>>();
    k_scan3    <<<(N_NODES + 255) / 256, 256>>>();
    k_scatter  <<<(N_EDGES + 255) / 256, 256>>>();
    k_permute  <<<(N_EDGES * EDGE_DIM + 255) / 256, 256>>>(edge_attr);

    // layer 1 (K = IN_DIM)
    k_linear<<<dim3(NB_M, 2), 256>>>(x,   W1n, b1n, pA,  N_NODES, 128, IN_DIM, IN_DIM + EDGE_DIM, 0, 0);
    k_linear<<<dim3(NB_M, 2), 256>>>(x,   W1r, b1r, ph0, N_NODES, 128, IN_DIM, IN_DIM,            0, 1);
    k_edge_conv<<<EB, 512>>>(W1n, IN_DIM + EDGE_DIM, IN_DIM, pA, ph0);

    // layer 2 (K = HID)
    k_linear<<<dim3(NB_M, 2), 256>>>(ph0, W2n, b2n, pA,  N_NODES, 128, HID, HID + EDGE_DIM, 0, 0);
    k_linear<<<dim3(NB_M, 2), 256>>>(ph0, W2r, b2r, ph1, N_NODES, 128, HID, HID,            0, 1);
    k_edge_conv<<<EB, 512>>>(W2n, HID + EDGE_DIM, HID, pA, ph1);

    // layer 3
    k_linear<<<dim3(NB_M, 2), 256>>>(ph1, W3n, b3n, pA,  N_NODES, 128, HID, HID + EDGE_DIM, 0, 0);
    k_linear<<<dim3(NB_M, 2), 256>>>(ph1, W3r, b3r, ph0, N_NODES, 128, HID, HID,            0, 1);
    k_edge_conv<<<EB, 512>>>(W3n, HID + EDGE_DIM, HID, pA, ph0);
    // h3 = ph0

    // gate MLP
    k_linear<<<dim3(NB_M, 1), 256>>>(ph0, Wg1, bg1, pg1,   N_NODES, 64, 128, 128, 0, 2);
    k_linear<<<dim3(NB_M, 1), 256>>>(pg1, Wg2, bg2, pg2,   N_NODES, 32, 64,  64,  0, 2);
    k_linear<<<dim3(NB_M, 1), 256>>>(pg2, Wg3, bg3, pgate, N_NODES, 1,  32,  32,  0, 0);

    // graph segments + attention readout (att written after the [G,5] preds)
    k_gcnt <<<(N_NODES + 255) / 256, 256>>>(batch);
    k_gscan<<<1, 32>>>();
    k_attn <<<N_GRAPHS, 128>>>(ph0, out + N_GRAPHS * 5);

    // head MLP
    k_concat<<<(N_GRAPHS * 256 + 255) / 256, 256>>>(u_soap, u_dimer);
    k_linear<<<dim3(1, 4), 256>>>(pe2, Wl1, bl1, po1, N_GRAPHS, 256, 256, 256, 0, 2);
    k_linear<<<dim3(1, 2), 256>>>(po1, Wl2, bl2, po2, N_GRAPHS, 128, 256, 256, 0, 2);
    k_linear<<<dim3(1, 1), 256>>>(po2, Wl3, bl3, po3, N_GRAPHS, 64,  128, 128, 0, 2);
    k_linear<<<dim3(1, 1), 256>>>(po3, Wl,  bl,  po4, N_GRAPHS, 4,   64,  64,  0, 0);
    k_out<<<1, 128>>>(out);
}